// round 2
// baseline (speedup 1.0000x reference)
#include <cuda_runtime.h>
#include <math.h>

// ---------------- problem constants ----------------
#define NB 8          // batch
#define CC 256        // channels
#define NGROUPS 16
#define GSIZE 16      // channels per group
#define GN_EPS 1e-5f

#define TOTHW   16800                 // 12800 + 3200 + 800
#define CLSBASE 0                     // cls_cat: [8, 16800, 20]
#define REGBASE 2688000               // reg_cat: [8, 67200, 1]
#define CTRBASE 3225600               // ctr_cat: [8, 16800, 1]

// scratch (device globals: no runtime allocation allowed)
__device__ float g_bufA[NB * CC * 12800];
__device__ float g_bufB[NB * CC * 12800];
__device__ float g_stats[NB * NGROUPS * 2];   // mean, rstd per (n, group)

// ============================================================
// Tower conv: 3x3, Cin=256 -> Cout=256, pad 1, NCHW.
// Block computes 128 output channels x (8 rows x 16 cols) pixels.
// grid = (W/16, ceil(H/8), N*2)  [z: n*2 + coTile]
// 256 threads: cog = tid>>4 (16), pxg = tid&15 (16).
// Thread: 8 channels (cog + 16*i) x 8 rows (col = pxg).
// ============================================================
__global__ __launch_bounds__(256) void conv3x3_c256(
    const float* __restrict__ in, const float* __restrict__ w,
    const float* __restrict__ bias, float* __restrict__ out,
    int H, int W)
{
    const int tx  = blockIdx.x * 16;
    const int ty  = blockIdx.y * 8;
    const int n   = blockIdx.z >> 1;
    const int co0 = (blockIdx.z & 1) * 128;
    const int tid = threadIdx.x;
    const int cog = tid >> 4;
    const int pxg = tid & 15;

    __shared__ float Ws[128 * 72];      // [co][ci(8)*9]
    __shared__ float Xs[8 * 10 * 20];   // [ci][row(10)][col pitch 20]

    float acc[8][8];
#pragma unroll
    for (int i = 0; i < 8; i++)
#pragma unroll
        for (int r = 0; r < 8; r++) acc[i][r] = 0.0f;

    const float* inN = in + (size_t)n * CC * H * W;

#pragma unroll 1
    for (int ci0 = 0; ci0 < CC; ci0 += 8) {
        // ---- load input tile (8 ci, 10x18 with halo, zero-padded) ----
        for (int l = tid; l < 8 * 10 * 18; l += 256) {
            int ci  = l / 180;
            int rem = l - ci * 180;
            int ry  = rem / 18;
            int cx  = rem - ry * 18;
            int gy = ty - 1 + ry, gx = tx - 1 + cx;
            float v = 0.0f;
            if (gy >= 0 && gy < H && gx >= 0 && gx < W)
                v = inN[((size_t)(ci0 + ci) * H + gy) * W + gx];
            Xs[ci * 200 + ry * 20 + cx] = v;
        }
        // ---- load weight chunk: 128 co x (8 ci x 9) ----
        const float* wg = w + (size_t)co0 * 2304 + (size_t)ci0 * 9;
        for (int l = tid; l < 128 * 72; l += 256) {
            int co = l / 72;
            int r  = l - co * 72;
            Ws[l] = wg[(size_t)co * 2304 + r];
        }
        __syncthreads();

#pragma unroll 1
        for (int ci = 0; ci < 8; ci++) {
            const float* xrow = &Xs[ci * 200];
            const int wb = cog * 72 + ci * 9;
#pragma unroll
            for (int k = 0; k < 9; k++) {
                const int ky = k / 3, kx = k - ky * 3;
                float xv[8];
#pragma unroll
                for (int r = 0; r < 8; r++)
                    xv[r] = xrow[(r + ky) * 20 + pxg + kx];
                float wv[8];
#pragma unroll
                for (int i = 0; i < 8; i++)
                    wv[i] = Ws[wb + i * (16 * 72) + k];
#pragma unroll
                for (int i = 0; i < 8; i++)
#pragma unroll
                    for (int r = 0; r < 8; r++)
                        acc[i][r] += wv[i] * xv[r];
            }
        }
        __syncthreads();
    }

#pragma unroll
    for (int i = 0; i < 8; i++) {
        const int co = co0 + cog + 16 * i;
        const float b = bias[co];
#pragma unroll
        for (int r = 0; r < 8; r++) {
            int gy = ty + r;
            if (gy < H)
                out[(((size_t)n * CC + co) * H + gy) * W + tx + pxg] = acc[i][r] + b;
        }
    }
}

// ============================================================
// GroupNorm stats: one block per (n, group). Double accumulation.
// ============================================================
__global__ __launch_bounds__(256) void gn_stats(
    const float* __restrict__ x, float* __restrict__ stats, int HW)
{
    const int g = blockIdx.x;              // 0..127
    const int n = g >> 4, grp = g & 15;
    const float* base = x + ((size_t)n * CC + grp * GSIZE) * HW;
    const int cnt = GSIZE * HW;

    double s = 0.0, ss = 0.0;
    for (int i = threadIdx.x; i < cnt; i += 256) {
        float v = base[i];
        s += v;
        ss += (double)v * v;
    }
    __shared__ double sh[512];
    sh[threadIdx.x] = s;
    sh[256 + threadIdx.x] = ss;
    __syncthreads();
    for (int off = 128; off > 0; off >>= 1) {
        if (threadIdx.x < off) {
            sh[threadIdx.x] += sh[threadIdx.x + off];
            sh[256 + threadIdx.x] += sh[256 + threadIdx.x + off];
        }
        __syncthreads();
    }
    if (threadIdx.x == 0) {
        double mean = sh[0] / cnt;
        double var  = sh[256] / cnt - mean * mean;
        stats[2 * g]     = (float)mean;
        stats[2 * g + 1] = rsqrtf((float)var + GN_EPS);
    }
}

// ============================================================
// GroupNorm normalize + affine + ReLU, in place.
// ============================================================
__global__ __launch_bounds__(256) void gn_norm(
    float* __restrict__ x, const float* __restrict__ stats,
    const float* __restrict__ gamma, const float* __restrict__ beta, int HW)
{
    const size_t total = (size_t)NB * CC * HW;
    const size_t stride = (size_t)gridDim.x * blockDim.x;
    for (size_t idx = (size_t)blockIdx.x * blockDim.x + threadIdx.x;
         idx < total; idx += stride) {
        size_t c_lin = idx / HW;            // n*256 + c
        int c = (int)(c_lin & 255);
        int n = (int)(c_lin >> 8);
        int g = n * NGROUPS + (c >> 4);
        float mean = stats[2 * g], rstd = stats[2 * g + 1];
        float v = (x[idx] - mean) * rstd * gamma[c] + beta[c];
        x[idx] = fmaxf(v, 0.0f);
    }
}

// ============================================================
// Output conv: 3x3, Cin=256 -> COUT (small), writes straight into
// the permuted/concatenated output layout.
// MODE 0: cls  -> out[(n*16800+pix)*20 + co] = v + b
// MODE 1: reg  -> out[REGBASE + (n*16800+pix)*4 + co] = relu(v + b)
// MODE 2: ctr  -> out[CTRBASE + n*16800 + pix] = v + b
// grid = (W/16, ceil(H/8), N); 256 threads, px = tid&127, half = tid>>7.
// ============================================================
template <int COUT, int MODE>
__global__ __launch_bounds__(256) void outconv(
    const float* __restrict__ in, const float* __restrict__ w,
    const float* __restrict__ bias, float* __restrict__ out,
    int H, int W, int poff)
{
    const int tx = blockIdx.x * 16;
    const int ty = blockIdx.y * 8;
    const int n  = blockIdx.z;
    const int tid = threadIdx.x;
    const int px  = tid & 127;
    const int half = tid >> 7;
    const int row = px >> 4;
    const int col = px & 15;

    constexpr int COH = (COUT + 1) / 2;
    const int cobase = half * COH;
    const int conum  = (COUT - cobase) < COH ? (COUT - cobase) : COH;

    __shared__ float Ws[COUT * 72];
    __shared__ float Xs[8 * 10 * 20];

    float acc[COH];
#pragma unroll
    for (int c = 0; c < COH; c++) acc[c] = 0.0f;

    const float* inN = in + (size_t)n * CC * H * W;

#pragma unroll 1
    for (int ci0 = 0; ci0 < CC; ci0 += 8) {
        for (int l = tid; l < 8 * 10 * 18; l += 256) {
            int ci  = l / 180;
            int rem = l - ci * 180;
            int ry  = rem / 18;
            int cx  = rem - ry * 18;
            int gy = ty - 1 + ry, gx = tx - 1 + cx;
            float v = 0.0f;
            if (gy >= 0 && gy < H && gx >= 0 && gx < W)
                v = inN[((size_t)(ci0 + ci) * H + gy) * W + gx];
            Xs[ci * 200 + ry * 20 + cx] = v;
        }
        const float* wg = w + (size_t)ci0 * 9;
        for (int l = tid; l < COUT * 72; l += 256) {
            int co = l / 72;
            int r  = l - co * 72;
            Ws[l] = wg[(size_t)co * 2304 + r];
        }
        __syncthreads();

#pragma unroll 1
        for (int ci = 0; ci < 8; ci++) {
            const float* xrow = &Xs[ci * 200];
#pragma unroll
            for (int k = 0; k < 9; k++) {
                const int ky = k / 3, kx = k - ky * 3;
                float x = xrow[(row + ky) * 20 + col + kx];
#pragma unroll
                for (int c = 0; c < COH; c++)
                    if (c < conum)
                        acc[c] += Ws[(cobase + c) * 72 + ci * 9 + k] * x;
            }
        }
        __syncthreads();
    }

    const int gy = ty + row;
    if (gy < H && conum > 0) {
        const int pix = poff + gy * W + tx + col;
        const size_t gp = (size_t)n * TOTHW + pix;
#pragma unroll
        for (int c = 0; c < COH; c++) {
            if (c >= conum) break;
            const int co = cobase + c;
            float v = acc[c] + bias[co];
            if (MODE == 0) {
                out[CLSBASE + gp * 20 + co] = v;
            } else if (MODE == 1) {
                out[REGBASE + gp * 4 + co] = fmaxf(v, 0.0f);
            } else {
                out[CTRBASE + gp] = v;
            }
        }
    }
}

// ============================================================
// host launcher
// ============================================================
extern "C" void kernel_launch(void* const* d_in, const int* in_sizes, int n_in,
                              void* d_out, int out_size)
{
    (void)in_sizes; (void)n_in; (void)out_size;

    const float* feat[3] = { (const float*)d_in[0], (const float*)d_in[1],
                             (const float*)d_in[2] };
    const float* cls_conv_w = (const float*)d_in[3];   // [2,256,256,3,3]
    const float* cls_conv_b = (const float*)d_in[4];   // [2,256]
    const float* cls_gn_g   = (const float*)d_in[5];
    const float* cls_gn_b   = (const float*)d_in[6];
    const float* cls_out_w  = (const float*)d_in[7];   // [20,256,3,3]
    const float* cls_out_b  = (const float*)d_in[8];
    const float* reg_conv_w = (const float*)d_in[9];
    const float* reg_conv_b = (const float*)d_in[10];
    const float* reg_gn_g   = (const float*)d_in[11];
    const float* reg_gn_b   = (const float*)d_in[12];
    const float* reg_out_w  = (const float*)d_in[13];  // [4,256,3,3]
    const float* reg_out_b  = (const float*)d_in[14];
    const float* ctr_w      = (const float*)d_in[15];  // [1,256,3,3]
    const float* ctr_b      = (const float*)d_in[16];

    float* out = (float*)d_out;

    float *bufA, *bufB, *stats;
    cudaGetSymbolAddress((void**)&bufA, g_bufA);
    cudaGetSymbolAddress((void**)&bufB, g_bufB);
    cudaGetSymbolAddress((void**)&stats, g_stats);

    const int LH[3] = {100, 50, 25};
    const int LW[3] = {128, 64, 32};
    const int LP[3] = {0, 12800, 16000};
    const size_t WSTRIDE = (size_t)CC * CC * 9;   // per-layer tower weight stride

    for (int L = 0; L < 3; L++) {
        const int H = LH[L], W = LW[L], HW = H * W, poff = LP[L];
        dim3 cgrid(W / 16, (H + 7) / 8, NB * 2);
        dim3 ogrid(W / 16, (H + 7) / 8, NB);
        const int nblk = 2048;

        // ---- classification tower ----
        conv3x3_c256<<<cgrid, 256>>>(feat[L], cls_conv_w, cls_conv_b, bufA, H, W);
        gn_stats<<<NB * NGROUPS, 256>>>(bufA, stats, HW);
        gn_norm<<<nblk, 256>>>(bufA, stats, cls_gn_g, cls_gn_b, HW);
        conv3x3_c256<<<cgrid, 256>>>(bufA, cls_conv_w + WSTRIDE, cls_conv_b + CC,
                                     bufB, H, W);
        gn_stats<<<NB * NGROUPS, 256>>>(bufB, stats, HW);
        gn_norm<<<nblk, 256>>>(bufB, stats, cls_gn_g + CC, cls_gn_b + CC, HW);
        outconv<20, 0><<<ogrid, 256>>>(bufB, cls_out_w, cls_out_b, out, H, W, poff);

        // ---- regression tower ----
        conv3x3_c256<<<cgrid, 256>>>(feat[L], reg_conv_w, reg_conv_b, bufA, H, W);
        gn_stats<<<NB * NGROUPS, 256>>>(bufA, stats, HW);
        gn_norm<<<nblk, 256>>>(bufA, stats, reg_gn_g, reg_gn_b, HW);
        conv3x3_c256<<<cgrid, 256>>>(bufA, reg_conv_w + WSTRIDE, reg_conv_b + CC,
                                     bufB, H, W);
        gn_stats<<<NB * NGROUPS, 256>>>(bufB, stats, HW);
        gn_norm<<<nblk, 256>>>(bufB, stats, reg_gn_g + CC, reg_gn_b + CC, HW);
        outconv<4, 1><<<ogrid, 256>>>(bufB, reg_out_w, reg_out_b, out, H, W, poff);
        outconv<1, 2><<<ogrid, 256>>>(bufB, ctr_w, ctr_b, out, H, W, poff);
    }
}